// round 14
// baseline (speedup 1.0000x reference)
#include <cuda_runtime.h>

typedef unsigned long long ull;

// Weights in global, built per replay by setup_kernel.
// Interleaved transposed layout (fusion weights AND WngT):
//   d = k*64 + h*32 + g*4 + e  <->  c = g*8 + h*4 + e   (h<2, e<4, g<8)
__device__ float g_WT[2][256 * 64];
__device__ float g_WngT[128 * 64];

__global__ void setup_kernel(const float* __restrict__ Wfp1,
                             const float* __restrict__ Wf1,
                             const float* __restrict__ Wng) {
    int tid = blockIdx.x * blockDim.x + threadIdx.x;
    int stride = gridDim.x * blockDim.x;
    for (int i = tid; i < 64 * 256; i += stride) {
        int c = i >> 8, k = i & 255;
        int g = c >> 3, h = (c >> 2) & 1, e = c & 3;
        g_WT[0][k * 64 + h * 32 + g * 4 + e] = Wfp1[i];
        g_WT[1][k * 64 + h * 32 + g * 4 + e] = Wf1[i];
    }
    for (int i = tid; i < 64 * 128; i += stride) {
        int c = i >> 7, k = i & 127;
        int g = c >> 3, h = (c >> 2) & 1, e = c & 3;
        g_WngT[k * 64 + h * 32 + g * 4 + e] = Wng[i];
    }
}

__device__ __forceinline__ float sigmoidf_(float x) {
    return __fdividef(1.0f, 1.0f + __expf(-x));
}
__device__ __forceinline__ float gatef_(float x, float rm) {
    return x * sigmoidf_(fabsf(x - rm));
}
__device__ __forceinline__ float leakyf_(float x) {
    return x > 0.0f ? x : 0.01f * x;
}
__device__ __forceinline__ void ffma2_(ull& d, ull a, ull b) {
    asm("fma.rn.f32x2 %0, %1, %2, %0;" : "+l"(d) : "l"(a), "l"(b));
}
__device__ __forceinline__ ull fmul2_(ull a, ull b) {
    ull r;
    asm("mul.rn.f32x2 %0, %1, %2;" : "=l"(r) : "l"(a), "l"(b));
    return r;
}
__device__ __forceinline__ ull dup2_(float x) {
    ull r;
    unsigned u = __float_as_uint(x);
    asm("mov.b64 %0, {%1, %1};" : "=l"(r) : "r"(u));
    return r;
}
__device__ __forceinline__ float2 unpk_(ull v) {
    float2 r;
    asm("mov.b64 {%0, %1}, %2;" : "=f"(r.x), "=f"(r.y) : "l"(v));
    return r;
}
__device__ __forceinline__ void st_dup2(float* p, float v) {
    *reinterpret_cast<float2*>(p) = make_float2(v, v);
}

// Copy 8192 floats global -> smem, coalesced.
__device__ __forceinline__ void copy8(float* __restrict__ dst,
                                      const float* __restrict__ src, int tid) {
    const float4* s = reinterpret_cast<const float4*>(src);
    float4* d = reinterpret_cast<float4*>(dst);
#pragma unroll
    for (int i = 0; i < 8; i++) d[tid + i * 256] = s[tid + i * 256];
}

// Stage three matvec weight sets (16x64 each) into sMvW[3][1024].
__device__ __forceinline__ void stage_mvw(float* __restrict__ sMvW,
                                          const float* __restrict__ Wx,
                                          const float* __restrict__ Wy,
                                          const float* __restrict__ Wz,
                                          int tid) {
    float4* d = reinterpret_cast<float4*>(sMvW);
    d[tid] = reinterpret_cast<const float4*>(Wx)[tid];
    d[256 + tid] = reinterpret_cast<const float4*>(Wy)[tid];
    d[512 + tid] = reinterpret_cast<const float4*>(Wz)[tid];
}

// Stage one modality (128 rows x 64 floats) into sIn[128][68], coalesced.
__device__ __forceinline__ void stage_in128(float* __restrict__ sIn,
                                            const float* __restrict__ src,
                                            int row0, int tid) {
    const float4* s =
        reinterpret_cast<const float4*>(src + (size_t)row0 * 64);
#pragma unroll
    for (int it = 0; it < 8; it++) {
        int i = tid + it * 256;
        *reinterpret_cast<float4*>(sIn + (i >> 4) * 68 + (i & 15) * 4) = s[i];
    }
}

// 4-output matvec + sigmoid; input and weights both in smem.
// q = lane&3 selects output quad; rloc = wid*8 + (lane>>2):
// weight LDS warp-uniform (broadcast), xv LDS spans 8 rows.
__device__ __forceinline__ void mv4s(const float* __restrict__ sIn,
                                     const float* __restrict__ sW16,
                                     const float* __restrict__ b, int rloc,
                                     int q, float h[4]) {
    ull acc[4] = {0, 0, 0, 0};
    const float* xr = sIn + rloc * 68;
#pragma unroll 4
    for (int k = 0; k < 64; k += 4) {
        ulonglong2 xv = *reinterpret_cast<const ulonglong2*>(xr + k);
#pragma unroll
        for (int j = 0; j < 4; j++) {
            ulonglong2 w = *reinterpret_cast<const ulonglong2*>(
                sW16 + (q * 4 + j) * 64 + k);
            ffma2_(acc[j], xv.x, w.x);
            ffma2_(acc[j], xv.y, w.y);
        }
    }
#pragma unroll
    for (int j = 0; j < 4; j++) {
        float2 p = unpk_(acc[j]);
        h[j] = sigmoidf_(p.x + p.y + __ldg(b + q * 4 + j));
    }
}

// Both 64-row matvec passes for one modality + pooled factor stores.
// kind: 0 -> mx pairs, 1 -> m2y, 2 -> mz pairs.
__device__ __forceinline__ void mv_pool2(
    const float* __restrict__ sIn, const float* __restrict__ sW16,
    const float* __restrict__ b, float* __restrict__ sDst, int kind, int rloc,
    int q) {
    float h[4];
#pragma unroll
    for (int p = 0; p < 2; p++) {
        int r = rloc + p * 64;
        mv4s(sIn, sW16, b, r, q, h);
        if (kind == 1) {
            st_dup2(sDst + q * 256 + 2 * r,
                    fmaxf(fmaxf(h[0], h[1]), fmaxf(h[2], h[3])));
        } else {
            st_dup2(sDst + (2 * q) * 256 + 2 * r, fmaxf(h[0], h[1]));
            st_dup2(sDst + (2 * q + 1) * 256 + 2 * r, fmaxf(h[2], h[3]));
        }
    }
}

// Fusion GEMM over one k-half (4 local ix), 4 rows x 8 cols per thread,
// all 256 threads cover 128 rows x 64 cols.
// F[k=(ix*4+iy)*8+t][r] = mx[ix]*m2y[iy]*mz[t]; mz table hoisted to regs.
__device__ __forceinline__ void gemm128(
    const float* __restrict__ sW_, const float* __restrict__ sMxd,
    const float* __restrict__ sM2yd, const float* __restrict__ sMzd, int r0,
    int g, int gix0, ull acc[4][4]) {
    ull mz2[8][4];
#pragma unroll
    for (int t = 0; t < 8; t++) {
        ulonglong2 za =
            *reinterpret_cast<const ulonglong2*>(sMzd + t * 256 + 2 * r0);
        ulonglong2 zb =
            *reinterpret_cast<const ulonglong2*>(sMzd + t * 256 + 2 * r0 + 4);
        mz2[t][0] = za.x; mz2[t][1] = za.y;
        mz2[t][2] = zb.x; mz2[t][3] = zb.y;
    }
#pragma unroll 1
    for (int ixl = 0; ixl < 4; ixl++) {
        ulonglong2 xa = *reinterpret_cast<const ulonglong2*>(
            sMxd + (gix0 + ixl) * 256 + 2 * r0);
        ulonglong2 xb = *reinterpret_cast<const ulonglong2*>(
            sMxd + (gix0 + ixl) * 256 + 2 * r0 + 4);
#pragma unroll
        for (int iy = 0; iy < 4; iy++) {
            ulonglong2 ya = *reinterpret_cast<const ulonglong2*>(
                sM2yd + iy * 256 + 2 * r0);
            ulonglong2 yb = *reinterpret_cast<const ulonglong2*>(
                sM2yd + iy * 256 + 2 * r0 + 4);
            ull P0 = fmul2_(xa.x, ya.x);
            ull P1 = fmul2_(xa.y, ya.y);
            ull P2 = fmul2_(xb.x, yb.x);
            ull P3 = fmul2_(xb.y, yb.y);
            const float* wrow = sW_ + (ixl * 4 + iy) * 512 + g * 4;
#pragma unroll
            for (int t = 0; t < 8; t++) {
                ulonglong2 w0 =
                    *reinterpret_cast<const ulonglong2*>(wrow + t * 64);
                ulonglong2 w1 =
                    *reinterpret_cast<const ulonglong2*>(wrow + t * 64 + 32);
                ull f0 = fmul2_(P0, mz2[t][0]);
                ull f1 = fmul2_(P1, mz2[t][1]);
                ull f2 = fmul2_(P2, mz2[t][2]);
                ull f3 = fmul2_(P3, mz2[t][3]);
                ffma2_(acc[0][0], f0, w0.x); ffma2_(acc[0][1], f0, w0.y);
                ffma2_(acc[0][2], f0, w1.x); ffma2_(acc[0][3], f0, w1.y);
                ffma2_(acc[1][0], f1, w0.x); ffma2_(acc[1][1], f1, w0.y);
                ffma2_(acc[1][2], f1, w1.x); ffma2_(acc[1][3], f1, w1.y);
                ffma2_(acc[2][0], f2, w0.x); ffma2_(acc[2][1], f2, w0.y);
                ffma2_(acc[2][2], f2, w1.x); ffma2_(acc[2][3], f2, w1.y);
                ffma2_(acc[3][0], f3, w0.x); ffma2_(acc[3][1], f3, w0.y);
                ffma2_(acc[3][2], f3, w1.x); ffma2_(acc[3][3], f3, w1.y);
            }
        }
    }
}

// Shared layout (floats):
//  sW    @ 0     : 8192   (one 32KB weight half / WngT)
//  sGT   @ 8192  : 16896  ([128 k][132], entry k*132 + r, r<128)
//  sMxd  @ 25088 : 2048   ([8][256] dup'd, 128 rows)
//  sM2yd @ 27136 : 1024   ([4][256])
//  sMzd  @ 28160 : 2048   ([8][256])
//  sIn   @ 30208 : 8704   ([128][68] staged inputs)
//  sMvW  @ 38912 : 3072   (3 x [16][64] matvec weights)
//  total 41984 floats = 167936 B -> 1 CTA/SM
#define OFF_GT 8192
#define OFF_MXD 25088
#define OFF_M2YD 27136
#define OFF_MZD 28160
#define OFF_IN 30208
#define OFF_MVW 38912
#define SMEM_FLOATS 41984

__global__ void __launch_bounds__(256) fusion_main(
    const float* __restrict__ a, const float* __restrict__ v,
    const float* __restrict__ l, const float* __restrict__ pa,
    const float* __restrict__ pv, const float* __restrict__ pl,
    const float* __restrict__ mean, const float* __restrict__ Wa,
    const float* __restrict__ ba, const float* __restrict__ Wv,
    const float* __restrict__ bv, const float* __restrict__ Wl,
    const float* __restrict__ bl, const float* __restrict__ Wap,
    const float* __restrict__ bap, const float* __restrict__ Wvp,
    const float* __restrict__ bvp, const float* __restrict__ Wlp,
    const float* __restrict__ blp, const float* __restrict__ bf1,
    const float* __restrict__ bfp1, const float* __restrict__ bng,
    const float* __restrict__ rm1, const float* __restrict__ rm2,
    float* __restrict__ out) {
    extern __shared__ __align__(16) float smem[];
    float* sW_ = smem;
    float* sGT = smem + OFF_GT;
    float* sMxd = smem + OFF_MXD;
    float* sM2yd = smem + OFF_M2YD;
    float* sMzd = smem + OFF_MZD;
    float* sIn = smem + OFF_IN;
    float* sMvW = smem + OFF_MVW;

    const int tid = threadIdx.x;
    const int row0 = blockIdx.x * 128;
    const int wid = tid >> 5, lane = tid & 31;
    const int q = lane & 3;                  // matvec output quad
    const int rloc = wid * 8 + (lane >> 2);  // matvec row (0..63 per pass)
    const int r0 = (tid >> 3) * 4;           // GEMM rows (4/thread, 0..124)
    const int g = tid & 7;                   // GEMM col group
    const int c0 = g * 8;

    // ---- P0: W0 half0 + mvW -> smem; gated mean -> sGT; f2 factors ----
    copy8(sW_, g_WT[0], tid);
    stage_mvw(sMvW, Wap, Wvp, Wlp, tid);
#pragma unroll
    for (int it = 0; it < 32; it++) {
        int i = tid + it * 256;  // 8192 = 64 cc x 128 rr
        int rr = i >> 6, cc = i & 63;
        sGT[(64 + cc) * 132 + rr] =
            gatef_(__ldg(mean + (row0 + rr) * 64 + cc), __ldg(rm1 + 64 + cc));
    }
    stage_in128(sIn, pa, row0, tid);
    __syncthreads();
    mv_pool2(sIn, sMvW, bap, sMxd, 0, rloc, q);
    __syncthreads();
    stage_in128(sIn, pv, row0, tid);
    __syncthreads();
    mv_pool2(sIn, sMvW + 1024, bvp, sM2yd, 1, rloc, q);
    __syncthreads();
    stage_in128(sIn, pl, row0, tid);
    __syncthreads();
    mv_pool2(sIn, sMvW + 2048, blp, sMzd, 2, rloc, q);
    __syncthreads();

    // ---- P1: GEMM1 (two k-halves) -> gate -> sGT rows 0..63 ----
    {
        ull acc[4][4] = {};
        gemm128(sW_, sMxd, sM2yd, sMzd, r0, g, 0, acc);
        __syncthreads();
        copy8(sW_, g_WT[0] + 8192, tid);
        __syncthreads();
        gemm128(sW_, sMxd, sM2yd, sMzd, r0, g, 4, acc);
#pragma unroll
        for (int j = 0; j < 4; j++) {
            int ca = c0 + 2 * j, cb = ca + 1;
            float bca = __ldg(bfp1 + ca), bcb = __ldg(bfp1 + cb);
            float rca = __ldg(rm1 + ca), rcb = __ldg(rm1 + cb);
            float2 p0 = unpk_(acc[0][j]), p1 = unpk_(acc[1][j]);
            float2 p2 = unpk_(acc[2][j]), p3 = unpk_(acc[3][j]);
            *reinterpret_cast<float4*>(sGT + ca * 132 + r0) =
                make_float4(gatef_(leakyf_(p0.x + bca), rca),
                            gatef_(leakyf_(p1.x + bca), rca),
                            gatef_(leakyf_(p2.x + bca), rca),
                            gatef_(leakyf_(p3.x + bca), rca));
            *reinterpret_cast<float4*>(sGT + cb * 132 + r0) =
                make_float4(gatef_(leakyf_(p0.y + bcb), rcb),
                            gatef_(leakyf_(p1.y + bcb), rcb),
                            gatef_(leakyf_(p2.y + bcb), rcb),
                            gatef_(leakyf_(p3.y + bcb), rcb));
        }
    }
    __syncthreads();

    // ---- P2: WngT + mvW(branch1) -> smem; fusion-1 factors ----
    copy8(sW_, g_WngT, tid);
    stage_mvw(sMvW, Wa, Wv, Wl, tid);
    stage_in128(sIn, a, row0, tid);
    __syncthreads();
    mv_pool2(sIn, sMvW, ba, sMxd, 0, rloc, q);
    __syncthreads();
    stage_in128(sIn, v, row0, tid);
    __syncthreads();
    mv_pool2(sIn, sMvW + 1024, bv, sM2yd, 1, rloc, q);
    __syncthreads();
    stage_in128(sIn, l, row0, tid);
    __syncthreads();
    mv_pool2(sIn, sMvW + 2048, bl, sMzd, 2, rloc, q);
    __syncthreads();

    // ---- P3: GEMM2 (K=128, 4r x 8c) -> out[:,0:64] ----
    {
        ull acc[4][4] = {};
#pragma unroll 4
        for (int k = 0; k < 128; k++) {
            float4 fv = *reinterpret_cast<const float4*>(sGT + k * 132 + r0);
            ull f0 = dup2_(fv.x), f1 = dup2_(fv.y);
            ull f2 = dup2_(fv.z), f3 = dup2_(fv.w);
            const float* wr = sW_ + k * 64 + g * 4;
            ulonglong2 w0 = *reinterpret_cast<const ulonglong2*>(wr);
            ulonglong2 w1 = *reinterpret_cast<const ulonglong2*>(wr + 32);
            ffma2_(acc[0][0], f0, w0.x); ffma2_(acc[0][1], f0, w0.y);
            ffma2_(acc[0][2], f0, w1.x); ffma2_(acc[0][3], f0, w1.y);
            ffma2_(acc[1][0], f1, w0.x); ffma2_(acc[1][1], f1, w0.y);
            ffma2_(acc[1][2], f1, w1.x); ffma2_(acc[1][3], f1, w1.y);
            ffma2_(acc[2][0], f2, w0.x); ffma2_(acc[2][1], f2, w0.y);
            ffma2_(acc[2][2], f2, w1.x); ffma2_(acc[2][3], f2, w1.y);
            ffma2_(acc[3][0], f3, w0.x); ffma2_(acc[3][1], f3, w0.y);
            ffma2_(acc[3][2], f3, w1.x); ffma2_(acc[3][3], f3, w1.y);
        }
        float4 bbA = __ldg(reinterpret_cast<const float4*>(bng + c0));
        float4 bbB = __ldg(reinterpret_cast<const float4*>(bng + c0 + 4));
        float4 rmA = __ldg(reinterpret_cast<const float4*>(rm2 + c0));
        float4 rmB = __ldg(reinterpret_cast<const float4*>(rm2 + c0 + 4));
#pragma unroll
        for (int i = 0; i < 4; i++) {
            float2 p0 = unpk_(acc[i][0]), p1 = unpk_(acc[i][1]);
            float2 p2 = unpk_(acc[i][2]), p3 = unpk_(acc[i][3]);
            float* orow = out + (row0 + r0 + i) * 128 + c0;
            *reinterpret_cast<float4*>(orow) =
                make_float4(gatef_(p0.x + bbA.x, rmA.x),
                            gatef_(p0.y + bbA.y, rmA.y),
                            gatef_(p1.x + bbA.z, rmA.z),
                            gatef_(p1.y + bbA.w, rmA.w));
            *reinterpret_cast<float4*>(orow + 4) =
                make_float4(gatef_(p2.x + bbB.x, rmB.x),
                            gatef_(p2.y + bbB.y, rmB.y),
                            gatef_(p3.x + bbB.z, rmB.z),
                            gatef_(p3.y + bbB.w, rmB.w));
        }
    }
    __syncthreads();

    // ---- P4: GEMM3 (two k-halves) -> out[:,64:128] ----
    copy8(sW_, g_WT[1], tid);
    __syncthreads();
    {
        ull acc[4][4] = {};
        gemm128(sW_, sMxd, sM2yd, sMzd, r0, g, 0, acc);
        __syncthreads();
        copy8(sW_, g_WT[1] + 8192, tid);
        __syncthreads();
        gemm128(sW_, sMxd, sM2yd, sMzd, r0, g, 4, acc);
        float4 bbA = __ldg(reinterpret_cast<const float4*>(bf1 + c0));
        float4 bbB = __ldg(reinterpret_cast<const float4*>(bf1 + c0 + 4));
        float4 rmA = __ldg(reinterpret_cast<const float4*>(rm2 + 64 + c0));
        float4 rmB = __ldg(reinterpret_cast<const float4*>(rm2 + 64 + c0 + 4));
#pragma unroll
        for (int i = 0; i < 4; i++) {
            float2 p0 = unpk_(acc[i][0]), p1 = unpk_(acc[i][1]);
            float2 p2 = unpk_(acc[i][2]), p3 = unpk_(acc[i][3]);
            float* orow = out + (row0 + r0 + i) * 128 + 64 + c0;
            *reinterpret_cast<float4*>(orow) =
                make_float4(gatef_(leakyf_(p0.x + bbA.x), rmA.x),
                            gatef_(leakyf_(p0.y + bbA.y), rmA.y),
                            gatef_(leakyf_(p1.x + bbA.z), rmA.z),
                            gatef_(leakyf_(p1.y + bbA.w), rmA.w));
            *reinterpret_cast<float4*>(orow + 4) =
                make_float4(gatef_(leakyf_(p2.x + bbB.x), rmB.x),
                            gatef_(leakyf_(p2.y + bbB.y), rmB.y),
                            gatef_(leakyf_(p3.x + bbB.z), rmB.z),
                            gatef_(leakyf_(p3.y + bbB.w), rmB.w));
        }
    }
}

extern "C" void kernel_launch(void* const* d_in, const int* in_sizes, int n_in,
                              void* d_out, int out_size) {
    const float* a    = (const float*)d_in[0];
    const float* v    = (const float*)d_in[1];
    const float* l    = (const float*)d_in[2];
    const float* pa   = (const float*)d_in[3];
    const float* pv   = (const float*)d_in[4];
    const float* pl   = (const float*)d_in[5];
    const float* mean = (const float*)d_in[6];
    const float* Wa   = (const float*)d_in[7];
    const float* ba   = (const float*)d_in[8];
    const float* Wv   = (const float*)d_in[9];
    const float* bv   = (const float*)d_in[10];
    const float* Wl   = (const float*)d_in[11];
    const float* bl   = (const float*)d_in[12];
    const float* Wap  = (const float*)d_in[13];
    const float* bap  = (const float*)d_in[14];
    const float* Wvp  = (const float*)d_in[15];
    const float* bvp  = (const float*)d_in[16];
    const float* Wlp  = (const float*)d_in[17];
    const float* blp  = (const float*)d_in[18];
    const float* Wf1  = (const float*)d_in[19];
    const float* bf1  = (const float*)d_in[20];
    const float* Wfp1 = (const float*)d_in[21];
    const float* bfp1 = (const float*)d_in[22];
    const float* Wng  = (const float*)d_in[23];
    const float* bng  = (const float*)d_in[24];
    const float* rm1  = (const float*)d_in[25];
    const float* rm2  = (const float*)d_in[26];

    int nrows = in_sizes[0] / 64;
    static int smem_set = 0;
    if (!smem_set) {
        cudaFuncSetAttribute(fusion_main,
                             cudaFuncAttributeMaxDynamicSharedMemorySize,
                             SMEM_FLOATS * 4);
        smem_set = 1;
    }

    setup_kernel<<<64, 256>>>(Wfp1, Wf1, Wng);
    fusion_main<<<nrows / 128, 256, SMEM_FLOATS * 4>>>(
        a, v, l, pa, pv, pl, mean, Wa, ba, Wv, bv, Wl, bl, Wap, bap, Wvp, bvp,
        Wlp, blp, bf1, bfp1, bng, rm1, rm2, (float*)d_out);
}

// round 15
// speedup vs baseline: 1.2033x; 1.2033x over previous
#include <cuda_runtime.h>

typedef unsigned long long ull;

// Plain transposed weights [k][c], built per replay by setup_kernel.
__device__ float g_WT[2][256 * 64];  // 0: Wfp1, 1: Wf1
__device__ float g_WngT[128 * 64];

__global__ void setup_kernel(const float* __restrict__ Wfp1,
                             const float* __restrict__ Wf1,
                             const float* __restrict__ Wng) {
    int tid = blockIdx.x * blockDim.x + threadIdx.x;
    int stride = gridDim.x * blockDim.x;
    for (int i = tid; i < 64 * 256; i += stride) {
        int c = i >> 8, k = i & 255;
        g_WT[0][k * 64 + c] = Wfp1[i];
        g_WT[1][k * 64 + c] = Wf1[i];
    }
    for (int i = tid; i < 64 * 128; i += stride) {
        int c = i >> 7, k = i & 127;
        g_WngT[k * 64 + c] = Wng[i];
    }
}

__device__ __forceinline__ float sigmoidf_(float x) {
    return __fdividef(1.0f, 1.0f + __expf(-x));
}
__device__ __forceinline__ float gatef_(float x, float rm) {
    return x * sigmoidf_(fabsf(x - rm));
}
__device__ __forceinline__ float leakyf_(float x) {
    return x > 0.0f ? x : 0.01f * x;
}
__device__ __forceinline__ void ffma2_(ull& d, ull a, ull b) {
    asm("fma.rn.f32x2 %0, %1, %2, %0;" : "+l"(d) : "l"(a), "l"(b));
}
__device__ __forceinline__ ull dup2_(float x) {
    ull r;
    unsigned u = __float_as_uint(x);
    asm("mov.b64 %0, {%1, %1};" : "=l"(r) : "r"(u));
    return r;
}
__device__ __forceinline__ float2 unpk_(ull v) {
    float2 r;
    asm("mov.b64 {%0, %1}, %2;" : "=f"(r.x), "=f"(r.y) : "l"(v));
    return r;
}

// Copy 8192 floats global -> smem, coalesced.
__device__ __forceinline__ void copy8(float* __restrict__ dst,
                                      const float* __restrict__ src, int tid) {
    const float4* s = reinterpret_cast<const float4*>(src);
    float4* d = reinterpret_cast<float4*>(dst);
#pragma unroll
    for (int i = 0; i < 8; i++) d[tid + i * 256] = s[tid + i * 256];
}

// Stage three matvec weight sets (16x64 each) into sMvW[3][1024].
__device__ __forceinline__ void stage_mvw(float* __restrict__ sMvW,
                                          const float* __restrict__ Wx,
                                          const float* __restrict__ Wy,
                                          const float* __restrict__ Wz,
                                          int tid) {
    float4* d = reinterpret_cast<float4*>(sMvW);
    d[tid] = reinterpret_cast<const float4*>(Wx)[tid];
    d[256 + tid] = reinterpret_cast<const float4*>(Wy)[tid];
    d[512 + tid] = reinterpret_cast<const float4*>(Wz)[tid];
}

// Stage one modality (64 rows x 64 floats) into sIn[64][68], coalesced.
__device__ __forceinline__ void stage_in(float* __restrict__ sIn,
                                         const float* __restrict__ src,
                                         int row0, int tid) {
    const float4* s =
        reinterpret_cast<const float4*>(src + (size_t)row0 * 64);
#pragma unroll
    for (int it = 0; it < 4; it++) {
        int i = tid + it * 256;
        *reinterpret_cast<float4*>(sIn + (i >> 4) * 68 + (i & 15) * 4) = s[i];
    }
}

// 4-output matvec + sigmoid; input and weights both in smem.
// q = lane&3 selects output quad; rloc = wid*8 + (lane>>2).
__device__ __forceinline__ void mv4s(const float* __restrict__ sIn,
                                     const float* __restrict__ sW16,
                                     const float* __restrict__ b, int rloc,
                                     int q, float h[4]) {
    ull acc[4] = {0, 0, 0, 0};
    const float* xr = sIn + rloc * 68;
#pragma unroll 4
    for (int k = 0; k < 64; k += 4) {
        ulonglong2 xv = *reinterpret_cast<const ulonglong2*>(xr + k);
#pragma unroll
        for (int j = 0; j < 4; j++) {
            ulonglong2 w = *reinterpret_cast<const ulonglong2*>(
                sW16 + (q * 4 + j) * 64 + k);
            ffma2_(acc[j], xv.x, w.x);
            ffma2_(acc[j], xv.y, w.y);
        }
    }
#pragma unroll
    for (int j = 0; j < 4; j++) {
        float2 p = unpk_(acc[j]);
        h[j] = sigmoidf_(p.x + p.y + __ldg(b + q * 4 + j));
    }
}

// Fusion GEMM over one k-half (4 local ix), thread tile 4 rows x 4 cols,
// warp footprint 16 rows x 32 cols -> weight read = 1 wavefront per k.
// F[k=(ix*4+iy)*8+t][r] = mx[ix]*m2y[iy]*mz[t]; factor tables plain floats.
__device__ __forceinline__ void gemm44(
    const float* __restrict__ sW_, const float* __restrict__ sMx,
    const float* __restrict__ sM2y, const float* __restrict__ sMz, int r0,
    int c0, int gix0, ull acc[4][2]) {
    float4 mz4[8];
#pragma unroll
    for (int t = 0; t < 8; t++)
        mz4[t] = *reinterpret_cast<const float4*>(sMz + t * 64 + r0);
    float4 my4[4];
#pragma unroll
    for (int iy = 0; iy < 4; iy++)
        my4[iy] = *reinterpret_cast<const float4*>(sM2y + iy * 64 + r0);
#pragma unroll 1
    for (int ixl = 0; ixl < 4; ixl++) {
        float4 mx4 = *reinterpret_cast<const float4*>(
            sMx + (gix0 + ixl) * 64 + r0);
#pragma unroll
        for (int iy = 0; iy < 4; iy++) {
            float P0 = mx4.x * my4[iy].x;
            float P1 = mx4.y * my4[iy].y;
            float P2 = mx4.z * my4[iy].z;
            float P3 = mx4.w * my4[iy].w;
            const float* wrow = sW_ + (ixl * 4 + iy) * 512 + c0;
#pragma unroll
            for (int t = 0; t < 8; t++) {
                ulonglong2 w =
                    *reinterpret_cast<const ulonglong2*>(wrow + t * 64);
                ull f0 = dup2_(P0 * mz4[t].x);
                ull f1 = dup2_(P1 * mz4[t].y);
                ull f2 = dup2_(P2 * mz4[t].z);
                ull f3 = dup2_(P3 * mz4[t].w);
                ffma2_(acc[0][0], f0, w.x); ffma2_(acc[0][1], f0, w.y);
                ffma2_(acc[1][0], f1, w.x); ffma2_(acc[1][1], f1, w.y);
                ffma2_(acc[2][0], f2, w.x); ffma2_(acc[2][1], f2, w.y);
                ffma2_(acc[3][0], f3, w.x); ffma2_(acc[3][1], f3, w.y);
            }
        }
    }
}

// Shared layout (floats):
//  sW    @ 0     : 8192   (one 32KB weight half / WngT)
//  sGT   @ 8192  : 8704   ([128 k][68], entry k*68 + r)
//  sMx   @ 16896 : 512    ([8][64] plain)
//  sM2y  @ 17408 : 256    ([4][64])
//  sMz   @ 17664 : 512    ([8][64])
//  sIn   @ 18176 : 4352   ([64][68] staged inputs)
//  sMvW  @ 22528 : 3072   (3 x [16][64] matvec weights)
//  total 25600 floats = 102400 B -> 2 CTAs/SM
#define OFF_GT 8192
#define OFF_MX 16896
#define OFF_M2Y 17408
#define OFF_MZ 17664
#define OFF_IN 18176
#define OFF_MVW 22528
#define SMEM_FLOATS 25600

__global__ void __launch_bounds__(256, 2) fusion_main(
    const float* __restrict__ a, const float* __restrict__ v,
    const float* __restrict__ l, const float* __restrict__ pa,
    const float* __restrict__ pv, const float* __restrict__ pl,
    const float* __restrict__ mean, const float* __restrict__ Wa,
    const float* __restrict__ ba, const float* __restrict__ Wv,
    const float* __restrict__ bv, const float* __restrict__ Wl,
    const float* __restrict__ bl, const float* __restrict__ Wap,
    const float* __restrict__ bap, const float* __restrict__ Wvp,
    const float* __restrict__ bvp, const float* __restrict__ Wlp,
    const float* __restrict__ blp, const float* __restrict__ bf1,
    const float* __restrict__ bfp1, const float* __restrict__ bng,
    const float* __restrict__ rm1, const float* __restrict__ rm2,
    float* __restrict__ out) {
    extern __shared__ __align__(16) float smem[];
    float* sW_ = smem;
    float* sGT = smem + OFF_GT;
    float* sMx = smem + OFF_MX;
    float* sM2y = smem + OFF_M2Y;
    float* sMz = smem + OFF_MZ;
    float* sIn = smem + OFF_IN;
    float* sMvW = smem + OFF_MVW;

    const int tid = threadIdx.x;
    const int row0 = blockIdx.x * 64;
    const int wid = tid >> 5, lane = tid & 31;
    const int q = lane & 3;                  // matvec output quad
    const int rloc = wid * 8 + (lane >> 2);  // matvec row
    // GEMM mapping: warp covers 16 rows x 32 cols; thread tile 4r x 4c.
    const int colhalf = wid & 1, rowgrp = wid >> 1;
    const int r0 = rowgrp * 16 + (lane >> 3) * 4;
    const int c0 = colhalf * 32 + (lane & 7) * 4;
    float h[4];

    // ---- P0: Wfp1T half0 + mvW -> smem; gated mean -> sGT; f2 factors ----
    copy8(sW_, g_WT[0], tid);
    stage_mvw(sMvW, Wap, Wvp, Wlp, tid);
#pragma unroll
    for (int it = 0; it < 16; it++) {
        int i = tid + it * 256;
        int rr = i >> 6, cc = i & 63;
        sGT[(64 + cc) * 68 + rr] =
            gatef_(__ldg(mean + (row0 + rr) * 64 + cc), __ldg(rm1 + 64 + cc));
    }
    stage_in(sIn, pa, row0, tid);
    __syncthreads();
    mv4s(sIn, sMvW, bap, rloc, q, h);
    sMx[(2 * q) * 64 + rloc] = fmaxf(h[0], h[1]);
    sMx[(2 * q + 1) * 64 + rloc] = fmaxf(h[2], h[3]);
    __syncthreads();
    stage_in(sIn, pv, row0, tid);
    __syncthreads();
    mv4s(sIn, sMvW + 1024, bvp, rloc, q, h);
    sM2y[q * 64 + rloc] = fmaxf(fmaxf(h[0], h[1]), fmaxf(h[2], h[3]));
    __syncthreads();
    stage_in(sIn, pl, row0, tid);
    __syncthreads();
    mv4s(sIn, sMvW + 2048, blp, rloc, q, h);
    sMz[(2 * q) * 64 + rloc] = fmaxf(h[0], h[1]);
    sMz[(2 * q + 1) * 64 + rloc] = fmaxf(h[2], h[3]);
    __syncthreads();

    // ---- P1: GEMM1 (two k-halves) -> gate -> sGT rows 0..63 ----
    {
        ull acc[4][2] = {};
        gemm44(sW_, sMx, sM2y, sMz, r0, c0, 0, acc);
        __syncthreads();
        copy8(sW_, g_WT[0] + 8192, tid);
        __syncthreads();
        gemm44(sW_, sMx, sM2y, sMz, r0, c0, 4, acc);
#pragma unroll
        for (int j = 0; j < 2; j++) {
            int ca = c0 + 2 * j, cb = ca + 1;
            float bca = __ldg(bfp1 + ca), bcb = __ldg(bfp1 + cb);
            float rca = __ldg(rm1 + ca), rcb = __ldg(rm1 + cb);
            float2 p0 = unpk_(acc[0][j]), p1 = unpk_(acc[1][j]);
            float2 p2 = unpk_(acc[2][j]), p3 = unpk_(acc[3][j]);
            *reinterpret_cast<float4*>(sGT + ca * 68 + r0) =
                make_float4(gatef_(leakyf_(p0.x + bca), rca),
                            gatef_(leakyf_(p1.x + bca), rca),
                            gatef_(leakyf_(p2.x + bca), rca),
                            gatef_(leakyf_(p3.x + bca), rca));
            *reinterpret_cast<float4*>(sGT + cb * 68 + r0) =
                make_float4(gatef_(leakyf_(p0.y + bcb), rcb),
                            gatef_(leakyf_(p1.y + bcb), rcb),
                            gatef_(leakyf_(p2.y + bcb), rcb),
                            gatef_(leakyf_(p3.y + bcb), rcb));
        }
    }
    __syncthreads();

    // ---- P2: WngT + mvW(branch1) -> smem; fusion-1 factors ----
    copy8(sW_, g_WngT, tid);
    stage_mvw(sMvW, Wa, Wv, Wl, tid);
    stage_in(sIn, a, row0, tid);
    __syncthreads();
    mv4s(sIn, sMvW, ba, rloc, q, h);
    sMx[(2 * q) * 64 + rloc] = fmaxf(h[0], h[1]);
    sMx[(2 * q + 1) * 64 + rloc] = fmaxf(h[2], h[3]);
    __syncthreads();
    stage_in(sIn, v, row0, tid);
    __syncthreads();
    mv4s(sIn, sMvW + 1024, bv, rloc, q, h);
    sM2y[q * 64 + rloc] = fmaxf(fmaxf(h[0], h[1]), fmaxf(h[2], h[3]));
    __syncthreads();
    stage_in(sIn, l, row0, tid);
    __syncthreads();
    mv4s(sIn, sMvW + 2048, bl, rloc, q, h);
    sMz[(2 * q) * 64 + rloc] = fmaxf(h[0], h[1]);
    sMz[(2 * q + 1) * 64 + rloc] = fmaxf(h[2], h[3]);
    __syncthreads();

    // ---- P3: GEMM2 (K=128, 4r x 4c) -> out[:,0:64] ----
    {
        ull acc[4][2] = {};
#pragma unroll 4
        for (int k = 0; k < 128; k++) {
            float4 fv = *reinterpret_cast<const float4*>(sGT + k * 68 + r0);
            ulonglong2 w =
                *reinterpret_cast<const ulonglong2*>(sW_ + k * 64 + c0);
            ull f0 = dup2_(fv.x), f1 = dup2_(fv.y);
            ull f2 = dup2_(fv.z), f3 = dup2_(fv.w);
            ffma2_(acc[0][0], f0, w.x); ffma2_(acc[0][1], f0, w.y);
            ffma2_(acc[1][0], f1, w.x); ffma2_(acc[1][1], f1, w.y);
            ffma2_(acc[2][0], f2, w.x); ffma2_(acc[2][1], f2, w.y);
            ffma2_(acc[3][0], f3, w.x); ffma2_(acc[3][1], f3, w.y);
        }
        float4 bb = __ldg(reinterpret_cast<const float4*>(bng + c0));
        float4 rr2 = __ldg(reinterpret_cast<const float4*>(rm2 + c0));
#pragma unroll
        for (int i = 0; i < 4; i++) {
            float2 pA = unpk_(acc[i][0]), pB = unpk_(acc[i][1]);
            *reinterpret_cast<float4*>(out + (row0 + r0 + i) * 128 + c0) =
                make_float4(gatef_(pA.x + bb.x, rr2.x),
                            gatef_(pA.y + bb.y, rr2.y),
                            gatef_(pB.x + bb.z, rr2.z),
                            gatef_(pB.y + bb.w, rr2.w));
        }
    }
    __syncthreads();

    // ---- P4: GEMM3 (two k-halves) -> out[:,64:128] ----
    copy8(sW_, g_WT[1], tid);
    __syncthreads();
    {
        ull acc[4][2] = {};
        gemm44(sW_, sMx, sM2y, sMz, r0, c0, 0, acc);
        __syncthreads();
        copy8(sW_, g_WT[1] + 8192, tid);
        __syncthreads();
        gemm44(sW_, sMx, sM2y, sMz, r0, c0, 4, acc);
        float4 bb = __ldg(reinterpret_cast<const float4*>(bf1 + c0));
        float4 rr2 = __ldg(reinterpret_cast<const float4*>(rm2 + 64 + c0));
#pragma unroll
        for (int i = 0; i < 4; i++) {
            float2 pA = unpk_(acc[i][0]), pB = unpk_(acc[i][1]);
            *reinterpret_cast<float4*>(out + (row0 + r0 + i) * 128 + 64 + c0) =
                make_float4(gatef_(leakyf_(pA.x + bb.x), rr2.x),
                            gatef_(leakyf_(pA.y + bb.y), rr2.y),
                            gatef_(leakyf_(pB.x + bb.z), rr2.z),
                            gatef_(leakyf_(pB.y + bb.w), rr2.w));
        }
    }
}

extern "C" void kernel_launch(void* const* d_in, const int* in_sizes, int n_in,
                              void* d_out, int out_size) {
    const float* a    = (const float*)d_in[0];
    const float* v    = (const float*)d_in[1];
    const float* l    = (const float*)d_in[2];
    const float* pa   = (const float*)d_in[3];
    const float* pv   = (const float*)d_in[4];
    const float* pl   = (const float*)d_in[5];
    const float* mean = (const float*)d_in[6];
    const float* Wa   = (const float*)d_in[7];
    const float* ba   = (const float*)d_in[8];
    const float* Wv   = (const float*)d_in[9];
    const float* bv   = (const float*)d_in[10];
    const float* Wl   = (const float*)d_in[11];
    const float* bl   = (const float*)d_in[12];
    const float* Wap  = (const float*)d_in[13];
    const float* bap  = (const float*)d_in[14];
    const float* Wvp  = (const float*)d_in[15];
    const float* bvp  = (const float*)d_in[16];
    const float* Wlp  = (const float*)d_in[17];
    const float* blp  = (const float*)d_in[18];
    const float* Wf1  = (const float*)d_in[19];
    const float* bf1  = (const float*)d_in[20];
    const float* Wfp1 = (const float*)d_in[21];
    const float* bfp1 = (const float*)d_in[22];
    const float* Wng  = (const float*)d_in[23];
    const float* bng  = (const float*)d_in[24];
    const float* rm1  = (const float*)d_in[25];
    const float* rm2  = (const float*)d_in[26];

    int nrows = in_sizes[0] / 64;
    static int smem_set = 0;
    if (!smem_set) {
        cudaFuncSetAttribute(fusion_main,
                             cudaFuncAttributeMaxDynamicSharedMemorySize,
                             SMEM_FLOATS * 4);
        smem_set = 1;
    }

    setup_kernel<<<64, 256>>>(Wfp1, Wf1, Wng);
    fusion_main<<<nrows / 64, 256, SMEM_FLOATS * 4>>>(
        a, v, l, pa, pv, pl, mean, Wa, ba, Wv, bv, Wl, bl, Wap, bap, Wvp, bvp,
        Wlp, blp, bf1, bfp1, bng, rm1, rm2, (float*)d_out);
}